// round 10
// baseline (speedup 1.0000x reference)
#include <cuda_runtime.h>
#include <cstdint>

#define WIRE_DIM   32
#define NUM_WIRES  64
#define ROW_ELEMS  (NUM_WIRES * WIRE_DIM)   // 2048 floats per batch row
#define WPB        4                        // warps per block = 2 pairs
#define PAIRS      (WPB / 2)
#define STAGES     2                        // ring depth per pair
#define ITERS      5                        // rows per pair
#define NTHREADS   (WPB * 32)
#define RPB        (PAIRS * ITERS)          // 10 rows per block

typedef unsigned long long u64;

// ---- packed f32x2 helpers ----
__device__ __forceinline__ u64 pack2f(float lo, float hi) {
    u64 r; asm("mov.b64 %0, {%1, %2};" : "=l"(r) : "f"(lo), "f"(hi)); return r;
}
__device__ __forceinline__ void ffma2(u64 &d, u64 a, u64 b) {
    asm("fma.rn.f32x2 %0, %1, %2, %0;" : "+l"(d) : "l"(a), "l"(b));
}
__device__ __forceinline__ float2 unpack2(u64 v) {
    float2 f; asm("mov.b64 {%0, %1}, %2;" : "=f"(f.x), "=f"(f.y) : "l"(v)); return f;
}

// ---- cp.async helpers ----
__device__ __forceinline__ void cp16(uint32_t dst_smem, const float* src) {
    asm volatile("cp.async.cg.shared.global [%0], [%1], 16;" :: "r"(dst_smem), "l"(src));
}
__device__ __forceinline__ void cp_commit() { asm volatile("cp.async.commit_group;"); }
template <int N> __device__ __forceinline__ void cp_wait() {
    asm volatile("cp.async.wait_group %0;" :: "n"(N));
}

// ---- weights in constant memory (uniform LDCU / lane-indexed LDC) ----
struct CPack {
    u64   Wlow[160];    // (W1[2p][h], W1[2p+1][h])       p=0..15  (rows 0..31, person half)
    u64   Whigh[160];   // (W1[32+2p][h], W1[32+2p+1][h]) p=0..15  (rows 32..63, wire half)
    float b1[10];
    float W2[10];
    float b2;
    float pad[5];
};
__constant__ CPack cc;
__device__   CPack g_pack;

__global__ void prep_kernel(const float* __restrict__ W1,
                            const float* __restrict__ b1,
                            const float* __restrict__ W2,
                            const float* __restrict__ b2)
{
    int i = threadIdx.x;
    if (i < 160) {
        int p = i / 10, h = i - 10 * p;
        g_pack.Wlow[i]  = pack2f(W1[(2 * p) * 10 + h],      W1[(2 * p + 1) * 10 + h]);
        g_pack.Whigh[i] = pack2f(W1[(32 + 2 * p) * 10 + h], W1[(32 + 2 * p + 1) * 10 + h]);
    } else if (i < 170) {
        int h = i - 160;
        g_pack.b1[h] = b1[h];
        g_pack.W2[h] = W2[h];
    } else if (i == 170) {
        g_pack.b2 = b2[0];
    }
}

__global__ __launch_bounds__(NTHREADS)
void trainer_kernel(const float* __restrict__ outputs,
                    const int* __restrict__ tests_i32,
                    float* __restrict__ out,
                    int B)
{
    // per pair: 2-stage x ring (16 KB); block total 32 KB + logits strip
    __shared__ __align__(16) float sx[PAIRS][STAGES][ROW_ELEMS];
    __shared__ __align__(16) float slog[PAIRS][NUM_WIRES];

    const int tid   = threadIdx.x;
    const int warp  = tid >> 5;
    const int lane  = tid & 31;
    const int pair  = warp >> 1;              // 0..PAIRS-1
    const int wq    = warp & 1;               // warp-in-pair: wires [32*wq, 32*wq+32)
    const int pt    = (wq << 5) | lane;       // thread id within the 64-thread pair

    // --- detect tests dtype (int64 pairs have zero high-words at odd slots) ---
    int hvv = tests_i32[2 * lane + 1];
    #pragma unroll
    for (int o = 16; o > 0; o >>= 1) hvv |= __shfl_xor_sync(0xffffffffu, hvv, o);
    const bool is_i64 = (hvv == 0);

    const int rbase = (blockIdx.x * PAIRS + pair) * ITERS;
    uint32_t sbuf[STAGES];
    #pragma unroll
    for (int s = 0; s < STAGES; s++)
        sbuf[s] = (uint32_t)__cvta_generic_to_shared(&sx[pair][s][0]);

    // pair-cooperative staging: 64 threads x 8 float4, rotated scatter
    auto stage_row = [&](int r, uint32_t sb) {
        const float* src = outputs + (size_t)r * ROW_ELEMS;
        #pragma unroll
        for (int t = 0; t < 8; t++) {
            int f = t * 64 + pt;               // float4 index 0..511
            int w = f >> 3;                    // wire
            int c = f & 7;                     // chunk within wire
            int off = w * 32 + (((c + w) & 7) << 2);
            cp16(sb + (uint32_t)(off << 2), src + (f << 2));
        }
    };

    if (rbase < B) stage_row(rbase, sbuf[0]);
    cp_commit();

    const float b2v = cc.b2;
    const int my_w  = (wq << 5) | lane;        // this lane's wire
    const int bx    = my_w * 32;               // float base of wire in row

    #pragma unroll
    for (int i = 0; i < ITERS; i++) {
        const int r = rbase + i;

        // prefetch next row (one commit per iteration; empty commits at tail)
        if (i + 1 < ITERS && r + 1 < B) stage_row(r + 1, sbuf[(i + 1) & 1]);
        cp_commit();
        cp_wait<1>();                          // row i complete (row i+1 may fly)
        __syncthreads();                       // whole pair sees row i; orders slog reuse

        if (r < B) {
            const float* xr = sx[pair][i & 1];

            // --- test indices (warp-uniform) ---
            int person, loc;
            if (is_i64) { person = tests_i32[4 * r]; loc = tests_i32[4 * r + 2]; }
            else        { person = tests_i32[2 * r]; loc = tests_i32[2 * r + 1]; }
            person &= 63;

            // --- person contribution: lanes 0..9 own h (lane-indexed LDC weights) ---
            const int hh = (lane < 10) ? lane : 0;
            u64 pcacc = pack2f(cc.b1[hh], 0.f);
            const float* px = &xr[person * 32];
            #pragma unroll
            for (int c = 0; c < 8; c++) {
                ulonglong2 pv = *(const ulonglong2*)&px[(((c + person) & 7) << 2)];
                ffma2(pcacc, pv.x, cc.Wlow[(2 * c) * 10 + hh]);
                ffma2(pcacc, pv.y, cc.Wlow[(2 * c + 1) * 10 + hh]);
            }
            float2 pcp2 = unpack2(pcacc);
            float pcv = pcp2.x + pcp2.y;

            // --- one wire per lane: 10 packed accumulators ---
            u64 acc[10];
            #pragma unroll
            for (int h = 0; h < 10; h++)
                acc[h] = pack2f(__shfl_sync(0xffffffffu, pcv, h), 0.f);

            #pragma unroll
            for (int c = 0; c < 8; c++) {
                const int rot = ((c + lane) & 7) << 2;          // (c+my_w)&7 == (c+lane)&7
                ulonglong2 xa = *(const ulonglong2*)&xr[bx + rot];  // d-pairs 2c, 2c+1
                #pragma unroll
                for (int pp = 0; pp < 2; pp++) {
                    const u64* wb = &cc.Whigh[(2 * c + pp) * 10];   // uniform -> LDCU
                    u64 xv = pp ? xa.y : xa.x;
                    #pragma unroll
                    for (int j = 0; j < 10; j++)
                        ffma2(acc[j], xv, wb[j]);
                }
            }

            // --- relu + output layer -> one logit, publish to pair strip ---
            float lg = b2v;
            #pragma unroll
            for (int h = 0; h < 10; h++) {
                float2 f = unpack2(acc[h]);
                lg += fmaxf(f.x + f.y, 0.f) * cc.W2[h];
            }
            slog[pair][my_w] = lg;
        }
        __syncthreads();                        // logits visible pair-wide

        if (r < B && wq == 0) {
            // --- final softmax over 64 logits (warp 0 of the pair) ---
            int loc;
            if (is_i64) loc = tests_i32[4 * r + 2];
            else        loc = tests_i32[2 * r + 1];

            float la = slog[pair][lane];
            float lb = slog[pair][lane + 32];

            float m = fmaxf(la, lb);
            #pragma unroll
            for (int o = 16; o > 0; o >>= 1)
                m = fmaxf(m, __shfl_xor_sync(0xffffffffu, m, o));
            float s = __expf(la - m) + __expf(lb - m);
            #pragma unroll
            for (int o = 16; o > 0; o >>= 1)
                s += __shfl_xor_sync(0xffffffffu, s, o);

            float cand = (loc >> 5) ? lb : la;
            cand = __shfl_sync(0xffffffffu, cand, loc & 31);

            if (lane == 0) out[r] = -(cand - m - __logf(s));
        }
    }
}

extern "C" void kernel_launch(void* const* d_in, const int* in_sizes, int n_in,
                              void* d_out, int out_size)
{
    const float* outputs = (const float*)d_in[0];
    const int*   tests   = (const int*)d_in[1];
    const float* W1      = (const float*)d_in[2];
    const float* b1      = (const float*)d_in[3];
    const float* W2      = (const float*)d_in[4];
    const float* b2      = (const float*)d_in[5];
    float* out = (float*)d_out;
    int B = out_size;

    prep_kernel<<<1, 192>>>(W1, b1, W2, b2);

    void* src_addr = nullptr;
    void* dst_addr = nullptr;
    cudaGetSymbolAddress(&src_addr, g_pack);
    cudaGetSymbolAddress(&dst_addr, cc);
    cudaMemcpyAsync(dst_addr, src_addr, sizeof(CPack), cudaMemcpyDeviceToDevice, 0);

    int blocks = (B + RPB - 1) / RPB;
    trainer_kernel<<<blocks, NTHREADS>>>(outputs, tests, out, B);
}

// round 13
// speedup vs baseline: 1.7346x; 1.7346x over previous
#include <cuda_runtime.h>
#include <cuda.h>
#include <cstdint>

#define WIRE_DIM   32
#define NUM_WIRES  64
#define ROW_ELEMS  (NUM_WIRES * WIRE_DIM)   // 2048 floats = 8 KB per batch row
#define WPB        4                        // warps per block (autonomous)
#define STAGES     2                        // per-warp ring depth
#define ITERS      5                        // rows per warp
#define NTHREADS   (WPB * 32)
#define RPB        (WPB * ITERS)            // 20 rows per block
#define ROW_BYTES  8192

typedef unsigned long long u64;

// ---- packed f32x2 helpers ----
__device__ __forceinline__ u64 pack2f(float lo, float hi) {
    u64 r; asm("mov.b64 %0, {%1, %2};" : "=l"(r) : "f"(lo), "f"(hi)); return r;
}
__device__ __forceinline__ void ffma2(u64 &d, u64 a, u64 b) {
    asm("fma.rn.f32x2 %0, %1, %2, %0;" : "+l"(d) : "l"(a), "l"(b));
}
__device__ __forceinline__ float2 unpack2(u64 v) {
    float2 f; asm("mov.b64 {%0, %1}, %2;" : "=f"(f.x), "=f"(f.y) : "l"(v)); return f;
}

// ---- mbarrier / TMA helpers ----
__device__ __forceinline__ void mbar_init(uint32_t mb, uint32_t cnt) {
    asm volatile("mbarrier.init.shared.b64 [%0], %1;" :: "r"(mb), "r"(cnt) : "memory");
}
__device__ __forceinline__ void mbar_expect_tx(uint32_t mb, uint32_t bytes) {
    asm volatile("mbarrier.arrive.expect_tx.shared.b64 _, [%0], %1;"
                 :: "r"(mb), "r"(bytes) : "memory");
}
__device__ __forceinline__ void mbar_wait(uint32_t mb, uint32_t parity) {
    asm volatile(
        "{\n\t.reg .pred P;\n"
        "LW_%=:\n\t"
        "mbarrier.try_wait.parity.acquire.cta.shared::cta.b64 P, [%0], %1, 0x989680;\n\t"
        "@P bra LD_%=;\n\t"
        "bra LW_%=;\n"
        "LD_%=:\n\t}"
        :: "r"(mb), "r"(parity) : "memory");
}
__device__ __forceinline__ void tma_load_row(uint32_t dst, const CUtensorMap* map,
                                             int wire_y, uint32_t mb) {
    asm volatile(
        "cp.async.bulk.tensor.2d.shared::cta.global.tile.mbarrier::complete_tx::bytes "
        "[%0], [%1, {%2, %3}], [%4];"
        :: "r"(dst), "l"(map), "r"(0), "r"(wire_y), "r"(mb) : "memory");
}

// ---- weights in constant memory ----
struct CPack {
    u64   Wlow[160];    // (W1[2p][h], W1[2p+1][h])       rows 0..31  (person half)
    u64   Whigh[160];   // (W1[32+2p][h], W1[32+2p+1][h]) rows 32..63 (wire half)
    float b1[10];
    float W2[10];
    float b2;
    float pad[5];
};
__constant__ CPack cc;
__device__   CPack g_pack;

__global__ void prep_kernel(const float* __restrict__ W1,
                            const float* __restrict__ b1,
                            const float* __restrict__ W2,
                            const float* __restrict__ b2)
{
    int i = threadIdx.x;
    if (i < 160) {
        int p = i / 10, h = i - 10 * p;
        g_pack.Wlow[i]  = pack2f(W1[(2 * p) * 10 + h],      W1[(2 * p + 1) * 10 + h]);
        g_pack.Whigh[i] = pack2f(W1[(32 + 2 * p) * 10 + h], W1[(32 + 2 * p + 1) * 10 + h]);
    } else if (i < 170) {
        int h = i - 160;
        g_pack.b1[h] = b1[h];
        g_pack.W2[h] = W2[h];
    } else if (i == 170) {
        g_pack.b2 = b2[0];
    }
}

__global__ __launch_bounds__(NTHREADS)
void trainer_kernel(const __grid_constant__ CUtensorMap tmap,
                    const int* __restrict__ tests_i32,
                    float* __restrict__ out,
                    int B)
{
    extern __shared__ char dynraw[];                 // WPB*STAGES*8KB + 1KB align slack
    __shared__ __align__(8) u64 mbar[WPB][STAGES];

    const int tid  = threadIdx.x;
    const int warp = tid >> 5;
    const int lane = tid & 31;

    // 1024B-align the ring base (TMA SW128 atom alignment)
    uint32_t base0 = (uint32_t)__cvta_generic_to_shared(dynraw);
    uint32_t pad   = ((base0 + 1023u) & ~1023u) - base0;
    float*   xall  = (float*)(dynraw + pad);
    const uint32_t xall_s = base0 + pad;

    if (tid == 0) {
        #pragma unroll
        for (int w = 0; w < WPB; w++)
            #pragma unroll
            for (int s = 0; s < STAGES; s++)
                mbar_init((uint32_t)__cvta_generic_to_shared(&mbar[w][s]), 1);
    }
    asm volatile("fence.proxy.async.shared::cta;" ::: "memory");
    __syncthreads();                                  // barriers visible; last block sync

    // --- detect tests dtype (int64 pairs have zero high-words at odd slots) ---
    int hvv = tests_i32[2 * lane + 1];
    #pragma unroll
    for (int o = 16; o > 0; o >>= 1) hvv |= __shfl_xor_sync(0xffffffffu, hvv, o);
    const bool is_i64 = (hvv == 0);

    const int rbase = blockIdx.x * RPB + warp * ITERS;
    uint32_t mb_s[STAGES], buf_s[STAGES];
    #pragma unroll
    for (int s = 0; s < STAGES; s++) {
        mb_s[s]  = (uint32_t)__cvta_generic_to_shared(&mbar[warp][s]);
        buf_s[s] = xall_s + (uint32_t)((warp * STAGES + s) * ROW_BYTES);
    }

    // prologue: row rbase -> stage 0
    if (lane == 0 && rbase < B) {
        mbar_expect_tx(mb_s[0], ROW_BYTES);
        tma_load_row(buf_s[0], &tmap, rbase * NUM_WIRES, mb_s[0]);
    }

    const float b2v = cc.b2;
    const int lw = lane & 7;                         // swizzle key for wires lane, lane+32

    #pragma unroll
    for (int i = 0; i < ITERS; i++) {
        const int r = rbase + i;

        // prefetch next row into the other stage (it was consumed in iter i-1)
        if (lane == 0 && i + 1 < ITERS && r + 1 < B) {
            const int s = (i + 1) & 1;
            mbar_expect_tx(mb_s[s], ROW_BYTES);
            tma_load_row(buf_s[s], &tmap, (r + 1) * NUM_WIRES, mb_s[s]);
        }
        if (r >= B) break;

        mbar_wait(mb_s[i & 1], (i >> 1) & 1);        // row i landed (acquire)
        const float* xr = xall + (warp * STAGES + (i & 1)) * ROW_ELEMS;

        // --- test indices (warp-uniform) ---
        int person, loc;
        if (is_i64) { person = tests_i32[4 * r]; loc = tests_i32[4 * r + 2]; }
        else        { person = tests_i32[2 * r]; loc = tests_i32[2 * r + 1]; }
        person &= 63;

        // --- person contribution: lanes 0..9 own h (lane-indexed LDC weights) ---
        // SW128: logical chunk c of wire w lives at granule (c ^ (w&7))
        const int hh = (lane < 10) ? lane : 0;
        const int pw = person & 7;
        u64 pcacc = pack2f(cc.b1[hh], 0.f);
        const float* px = &xr[person * 32];
        #pragma unroll
        for (int c = 0; c < 8; c++) {
            ulonglong2 pv = *(const ulonglong2*)&px[((c ^ pw) << 2)];   // broadcast
            ffma2(pcacc, pv.x, cc.Wlow[(2 * c) * 10 + hh]);
            ffma2(pcacc, pv.y, cc.Wlow[(2 * c + 1) * 10 + hh]);
        }
        float2 pcp2 = unpack2(pcacc);
        float pcv = pcp2.x + pcp2.y;

        // --- init accumulators: acc[h] = (pc[h], 0) for wires lane and lane+32 ---
        u64 accA[10], accB[10];
        #pragma unroll
        for (int h = 0; h < 10; h++) {
            u64 p = pack2f(__shfl_sync(0xffffffffu, pcv, h), 0.f);
            accA[h] = p; accB[h] = p;
        }

        // --- main MLP: swizzled LDS.128 (conflict-free), weights via uniform LDCU ---
        const int bA = lane * 32;
        const int bB = (lane + 32) * 32;

        #pragma unroll
        for (int c = 0; c < 8; c++) {
            const int g = ((c ^ lw) << 2);
            ulonglong2 xa = *(const ulonglong2*)&xr[bA + g];   // d-pairs 2c, 2c+1
            ulonglong2 xb = *(const ulonglong2*)&xr[bB + g];

            #pragma unroll
            for (int pp = 0; pp < 2; pp++) {
                const u64* wb = &cc.Whigh[(2 * c + pp) * 10];  // uniform -> LDCU
                u64 xav = pp ? xa.y : xa.x;
                u64 xbv = pp ? xb.y : xb.x;
                #pragma unroll
                for (int j = 0; j < 10; j++) {
                    u64 w = wb[j];
                    ffma2(accA[j], xav, w);
                    ffma2(accB[j], xbv, w);
                }
            }
        }

        // --- relu + output layer -> two logits per lane ---
        float la = b2v, lb = b2v;
        #pragma unroll
        for (int h = 0; h < 10; h++) {
            float w2h = cc.W2[h];
            float2 fa = unpack2(accA[h]);
            float2 fb = unpack2(accB[h]);
            la += fmaxf(fa.x + fa.y, 0.f) * w2h;
            lb += fmaxf(fb.x + fb.y, 0.f) * w2h;
        }

        // --- warp log-softmax over 64 logits, pick location ---
        float m = fmaxf(la, lb);
        #pragma unroll
        for (int o = 16; o > 0; o >>= 1)
            m = fmaxf(m, __shfl_xor_sync(0xffffffffu, m, o));
        float s = __expf(la - m) + __expf(lb - m);
        #pragma unroll
        for (int o = 16; o > 0; o >>= 1)
            s += __shfl_xor_sync(0xffffffffu, s, o);

        float cand = (loc >> 5) ? lb : la;     // wire w -> lane (w&31), slot (w>>5)
        cand = __shfl_sync(0xffffffffu, cand, loc & 31);

        if (lane == 0) out[r] = -(cand - m - __logf(s));
    }
}

extern "C" void kernel_launch(void* const* d_in, const int* in_sizes, int n_in,
                              void* d_out, int out_size)
{
    const float* outputs = (const float*)d_in[0];
    const int*   tests   = (const int*)d_in[1];
    const float* W1      = (const float*)d_in[2];
    const float* b1      = (const float*)d_in[3];
    const float* W2      = (const float*)d_in[4];
    const float* b2      = (const float*)d_in[5];
    float* out = (float*)d_out;
    int B = out_size;

    // --- weights -> constant memory ---
    prep_kernel<<<1, 192>>>(W1, b1, W2, b2);
    void *src_addr = nullptr, *dst_addr = nullptr;
    cudaGetSymbolAddress(&src_addr, g_pack);
    cudaGetSymbolAddress(&dst_addr, cc);
    cudaMemcpyAsync(dst_addr, src_addr, sizeof(CPack), cudaMemcpyDeviceToDevice, 0);

    // --- build TMA descriptor (driver entry point; no -lcuda needed) ---
    typedef CUresult (*EncodeFn)(CUtensorMap*, CUtensorMapDataType, cuuint32_t, void*,
                                 const cuuint64_t*, const cuuint64_t*, const cuuint32_t*,
                                 const cuuint32_t*, CUtensorMapInterleave, CUtensorMapSwizzle,
                                 CUtensorMapL2promotion, CUtensorMapFloatOOBfill);
    void* fn = nullptr;
    cudaDriverEntryPointQueryResult qres;
    cudaGetDriverEntryPoint("cuTensorMapEncodeTiled", &fn, cudaEnableDefault, &qres);

    CUtensorMap tmap;
    cuuint64_t dims[2]    = {128, (cuuint64_t)B * NUM_WIRES};  // [row bytes, total wires]
    cuuint64_t strides[1] = {128};
    cuuint32_t box[2]     = {128, NUM_WIRES};                  // one batch row = 8 KB
    cuuint32_t estr[2]    = {1, 1};
    ((EncodeFn)fn)(&tmap, CU_TENSOR_MAP_DATA_TYPE_UINT8, 2, (void*)outputs,
                   dims, strides, box, estr,
                   CU_TENSOR_MAP_INTERLEAVE_NONE, CU_TENSOR_MAP_SWIZZLE_128B,
                   CU_TENSOR_MAP_L2_PROMOTION_L2_128B, CU_TENSOR_MAP_FLOAT_OOB_FILL_NONE);

    // --- launch: dynamic smem ring (4 warps x 2 stages x 8 KB) + align slack ---
    const int dyn = WPB * STAGES * ROW_BYTES + 1024;
    cudaFuncSetAttribute(trainer_kernel, cudaFuncAttributeMaxDynamicSharedMemorySize, dyn);
    int blocks = (B + RPB - 1) / RPB;
    trainer_kernel<<<blocks, NTHREADS, dyn>>>(tmap, tests, out, B);
}

// round 14
// speedup vs baseline: 1.7551x; 1.0118x over previous
#include <cuda_runtime.h>
#include <cuda.h>
#include <cstdint>

#define WIRE_DIM   32
#define NUM_WIRES  64
#define ROW_ELEMS  (NUM_WIRES * WIRE_DIM)   // 2048 floats = 8 KB per batch row
#define WPB        2                        // warps per block (autonomous)
#define STAGES     3                        // per-warp ring depth: 2 rows in flight
#define ITERS      7                        // rows per warp
#define NTHREADS   (WPB * 32)
#define RPB        (WPB * ITERS)            // 14 rows per block
#define ROW_BYTES  8192

typedef unsigned long long u64;

// ---- packed f32x2 helpers ----
__device__ __forceinline__ u64 pack2f(float lo, float hi) {
    u64 r; asm("mov.b64 %0, {%1, %2};" : "=l"(r) : "f"(lo), "f"(hi)); return r;
}
__device__ __forceinline__ void ffma2(u64 &d, u64 a, u64 b) {
    asm("fma.rn.f32x2 %0, %1, %2, %0;" : "+l"(d) : "l"(a), "l"(b));
}
__device__ __forceinline__ float2 unpack2(u64 v) {
    float2 f; asm("mov.b64 {%0, %1}, %2;" : "=f"(f.x), "=f"(f.y) : "l"(v)); return f;
}

// ---- mbarrier / TMA helpers ----
__device__ __forceinline__ void mbar_init(uint32_t mb, uint32_t cnt) {
    asm volatile("mbarrier.init.shared.b64 [%0], %1;" :: "r"(mb), "r"(cnt) : "memory");
}
__device__ __forceinline__ void mbar_expect_tx(uint32_t mb, uint32_t bytes) {
    asm volatile("mbarrier.arrive.expect_tx.shared.b64 _, [%0], %1;"
                 :: "r"(mb), "r"(bytes) : "memory");
}
__device__ __forceinline__ void mbar_wait(uint32_t mb, uint32_t parity) {
    asm volatile(
        "{\n\t.reg .pred P;\n"
        "LW_%=:\n\t"
        "mbarrier.try_wait.parity.acquire.cta.shared::cta.b64 P, [%0], %1, 0x989680;\n\t"
        "@P bra LD_%=;\n\t"
        "bra LW_%=;\n"
        "LD_%=:\n\t}"
        :: "r"(mb), "r"(parity) : "memory");
}
__device__ __forceinline__ void tma_load_row(uint32_t dst, const CUtensorMap* map,
                                             int wire_y, uint32_t mb) {
    asm volatile(
        "cp.async.bulk.tensor.2d.shared::cta.global.tile.mbarrier::complete_tx::bytes "
        "[%0], [%1, {%2, %3}], [%4];"
        :: "r"(dst), "l"(map), "r"(0), "r"(wire_y), "r"(mb) : "memory");
}

// ---- weights in constant memory ----
struct CPack {
    u64   Wlow[160];    // (W1[2p][h], W1[2p+1][h])       rows 0..31  (person half)
    u64   Whigh[160];   // (W1[32+2p][h], W1[32+2p+1][h]) rows 32..63 (wire half)
    float b1[10];
    float W2[10];
    float b2;
    float pad[5];
};
__constant__ CPack cc;
__device__   CPack g_pack;

__global__ void prep_kernel(const float* __restrict__ W1,
                            const float* __restrict__ b1,
                            const float* __restrict__ W2,
                            const float* __restrict__ b2)
{
    int i = threadIdx.x;
    if (i < 160) {
        int p = i / 10, h = i - 10 * p;
        g_pack.Wlow[i]  = pack2f(W1[(2 * p) * 10 + h],      W1[(2 * p + 1) * 10 + h]);
        g_pack.Whigh[i] = pack2f(W1[(32 + 2 * p) * 10 + h], W1[(32 + 2 * p + 1) * 10 + h]);
    } else if (i < 170) {
        int h = i - 160;
        g_pack.b1[h] = b1[h];
        g_pack.W2[h] = W2[h];
    } else if (i == 170) {
        g_pack.b2 = b2[0];
    }
}

__global__ __launch_bounds__(NTHREADS)
void trainer_kernel(const __grid_constant__ CUtensorMap tmap,
                    const int* __restrict__ tests_i32,
                    float* __restrict__ out,
                    int B)
{
    extern __shared__ char dynraw[];                 // WPB*STAGES*8KB + 1KB align slack
    __shared__ __align__(8) u64 mbar[WPB][STAGES];

    const int tid  = threadIdx.x;
    const int warp = tid >> 5;
    const int lane = tid & 31;

    // 1024B-align the ring base (TMA SW128 atom alignment)
    uint32_t base0 = (uint32_t)__cvta_generic_to_shared(dynraw);
    uint32_t pad   = ((base0 + 1023u) & ~1023u) - base0;
    float*   xall  = (float*)(dynraw + pad);
    const uint32_t xall_s = base0 + pad;

    if (tid == 0) {
        #pragma unroll
        for (int w = 0; w < WPB; w++)
            #pragma unroll
            for (int s = 0; s < STAGES; s++)
                mbar_init((uint32_t)__cvta_generic_to_shared(&mbar[w][s]), 1);
    }
    asm volatile("fence.proxy.async.shared::cta;" ::: "memory");
    __syncthreads();                                  // barriers visible; last block sync

    // --- detect tests dtype (int64 pairs have zero high-words at odd slots) ---
    int hvv = tests_i32[2 * lane + 1];
    #pragma unroll
    for (int o = 16; o > 0; o >>= 1) hvv |= __shfl_xor_sync(0xffffffffu, hvv, o);
    const bool is_i64 = (hvv == 0);

    const int rbase = blockIdx.x * RPB + warp * ITERS;
    uint32_t mb_s[STAGES], buf_s[STAGES];
    #pragma unroll
    for (int s = 0; s < STAGES; s++) {
        mb_s[s]  = (uint32_t)__cvta_generic_to_shared(&mbar[warp][s]);
        buf_s[s] = xall_s + (uint32_t)((warp * STAGES + s) * ROW_BYTES);
    }

    // prologue: rows rbase, rbase+1 -> stages 0, 1 (two rows in flight)
    if (lane == 0) {
        if (rbase < B) {
            mbar_expect_tx(mb_s[0], ROW_BYTES);
            tma_load_row(buf_s[0], &tmap, rbase * NUM_WIRES, mb_s[0]);
        }
        if (rbase + 1 < B && 1 < ITERS) {
            mbar_expect_tx(mb_s[1], ROW_BYTES);
            tma_load_row(buf_s[1], &tmap, (rbase + 1) * NUM_WIRES, mb_s[1]);
        }
    }

    const float b2v = cc.b2;
    const int lw = lane & 7;                         // swizzle key for wires lane, lane+32

    #pragma unroll
    for (int i = 0; i < ITERS; i++) {
        const int r = rbase + i;

        // prefetch row i+2 (keeps 2 rows in flight through the compute phase)
        if (lane == 0 && i + 2 < ITERS && r + 2 < B) {
            const int s = (i + 2) % STAGES;
            mbar_expect_tx(mb_s[s], ROW_BYTES);
            tma_load_row(buf_s[s], &tmap, (r + 2) * NUM_WIRES, mb_s[s]);
        }
        if (r >= B) break;

        const int st = i % STAGES;
        mbar_wait(mb_s[st], (i / STAGES) & 1);       // row i landed (acquire)
        const float* xr = xall + (warp * STAGES + st) * ROW_ELEMS;

        // --- test indices (warp-uniform) ---
        int person, loc;
        if (is_i64) { person = tests_i32[4 * r]; loc = tests_i32[4 * r + 2]; }
        else        { person = tests_i32[2 * r]; loc = tests_i32[2 * r + 1]; }
        person &= 63;

        // --- person contribution: lanes 0..9 own h (lane-indexed LDC weights) ---
        // SW128: logical chunk c of wire w lives at granule (c ^ (w&7))
        const int hh = (lane < 10) ? lane : 0;
        const int pw = person & 7;
        u64 pcacc = pack2f(cc.b1[hh], 0.f);
        const float* px = &xr[person * 32];
        #pragma unroll
        for (int c = 0; c < 8; c++) {
            ulonglong2 pv = *(const ulonglong2*)&px[((c ^ pw) << 2)];   // broadcast
            ffma2(pcacc, pv.x, cc.Wlow[(2 * c) * 10 + hh]);
            ffma2(pcacc, pv.y, cc.Wlow[(2 * c + 1) * 10 + hh]);
        }
        float2 pcp2 = unpack2(pcacc);
        float pcv = pcp2.x + pcp2.y;

        // --- init accumulators: acc[h] = (pc[h], 0) for wires lane and lane+32 ---
        u64 accA[10], accB[10];
        #pragma unroll
        for (int h = 0; h < 10; h++) {
            u64 p = pack2f(__shfl_sync(0xffffffffu, pcv, h), 0.f);
            accA[h] = p; accB[h] = p;
        }

        // --- main MLP: swizzled LDS.128 (conflict-free), weights via uniform LDCU ---
        const int bA = lane * 32;
        const int bB = (lane + 32) * 32;

        #pragma unroll
        for (int c = 0; c < 8; c++) {
            const int g = ((c ^ lw) << 2);
            ulonglong2 xa = *(const ulonglong2*)&xr[bA + g];   // d-pairs 2c, 2c+1
            ulonglong2 xb = *(const ulonglong2*)&xr[bB + g];

            #pragma unroll
            for (int pp = 0; pp < 2; pp++) {
                const u64* wb = &cc.Whigh[(2 * c + pp) * 10];  // uniform -> LDCU
                u64 xav = pp ? xa.y : xa.x;
                u64 xbv = pp ? xb.y : xb.x;
                #pragma unroll
                for (int j = 0; j < 10; j++) {
                    u64 w = wb[j];
                    ffma2(accA[j], xav, w);
                    ffma2(accB[j], xbv, w);
                }
            }
        }

        // --- relu + output layer -> two logits per lane ---
        float la = b2v, lb = b2v;
        #pragma unroll
        for (int h = 0; h < 10; h++) {
            float w2h = cc.W2[h];
            float2 fa = unpack2(accA[h]);
            float2 fb = unpack2(accB[h]);
            la += fmaxf(fa.x + fa.y, 0.f) * w2h;
            lb += fmaxf(fb.x + fb.y, 0.f) * w2h;
        }

        // --- warp log-softmax over 64 logits, pick location ---
        float m = fmaxf(la, lb);
        #pragma unroll
        for (int o = 16; o > 0; o >>= 1)
            m = fmaxf(m, __shfl_xor_sync(0xffffffffu, m, o));
        float s = __expf(la - m) + __expf(lb - m);
        #pragma unroll
        for (int o = 16; o > 0; o >>= 1)
            s += __shfl_xor_sync(0xffffffffu, s, o);

        float cand = (loc >> 5) ? lb : la;     // wire w -> lane (w&31), slot (w>>5)
        cand = __shfl_sync(0xffffffffu, cand, loc & 31);

        if (lane == 0) out[r] = -(cand - m - __logf(s));
    }
}

extern "C" void kernel_launch(void* const* d_in, const int* in_sizes, int n_in,
                              void* d_out, int out_size)
{
    const float* outputs = (const float*)d_in[0];
    const int*   tests   = (const int*)d_in[1];
    const float* W1      = (const float*)d_in[2];
    const float* b1      = (const float*)d_in[3];
    const float* W2      = (const float*)d_in[4];
    const float* b2      = (const float*)d_in[5];
    float* out = (float*)d_out;
    int B = out_size;

    // --- weights -> constant memory ---
    prep_kernel<<<1, 192>>>(W1, b1, W2, b2);
    void *src_addr = nullptr, *dst_addr = nullptr;
    cudaGetSymbolAddress(&src_addr, g_pack);
    cudaGetSymbolAddress(&dst_addr, cc);
    cudaMemcpyAsync(dst_addr, src_addr, sizeof(CPack), cudaMemcpyDeviceToDevice, 0);

    // --- build TMA descriptor (driver entry point; no -lcuda needed) ---
    typedef CUresult (*EncodeFn)(CUtensorMap*, CUtensorMapDataType, cuuint32_t, void*,
                                 const cuuint64_t*, const cuuint64_t*, const cuuint32_t*,
                                 const cuuint32_t*, CUtensorMapInterleave, CUtensorMapSwizzle,
                                 CUtensorMapL2promotion, CUtensorMapFloatOOBfill);
    void* fn = nullptr;
    cudaDriverEntryPointQueryResult qres;
    cudaGetDriverEntryPoint("cuTensorMapEncodeTiled", &fn, cudaEnableDefault, &qres);

    CUtensorMap tmap;
    cuuint64_t dims[2]    = {128, (cuuint64_t)B * NUM_WIRES};  // [row bytes, total wires]
    cuuint64_t strides[1] = {128};
    cuuint32_t box[2]     = {128, NUM_WIRES};                  // one batch row = 8 KB
    cuuint32_t estr[2]    = {1, 1};
    ((EncodeFn)fn)(&tmap, CU_TENSOR_MAP_DATA_TYPE_UINT8, 2, (void*)outputs,
                   dims, strides, box, estr,
                   CU_TENSOR_MAP_INTERLEAVE_NONE, CU_TENSOR_MAP_SWIZZLE_128B,
                   CU_TENSOR_MAP_L2_PROMOTION_L2_128B, CU_TENSOR_MAP_FLOAT_OOB_FILL_NONE);

    // --- launch: dynamic smem ring (2 warps x 3 stages x 8 KB) + align slack ---
    const int dyn = WPB * STAGES * ROW_BYTES + 1024;
    cudaFuncSetAttribute(trainer_kernel, cudaFuncAttributeMaxDynamicSharedMemorySize, dyn);
    int blocks = (B + RPB - 1) / RPB;
    trainer_kernel<<<blocks, NTHREADS, dyn>>>(tmap, tests, out, B);
}